// round 2
// baseline (speedup 1.0000x reference)
#include <cuda_runtime.h>

#define NNODE 50000
#define NEDGE 800000
#define NEG_SLOPE 0.2f
#define BN_EPS 1e-5f
#define INV_SQRT2 0.7071067811865476f

// ---------------- scratch (device globals: no allocations allowed) -------------
__device__ float g_h1  [NNODE * 128];
__device__ float g_out1[NNODE * 128];   // raw msg accum -> normalized in BN
__device__ float g_h2  [NNODE * 128];
__device__ float g_out2[NNODE * 128];
__device__ float g_res [NNODE * 128];
__device__ float g_z   [NNODE * 128];
__device__ float g_as1[NNODE * 4];
__device__ float g_ad1[NNODE * 4];
__device__ float g_den1[NNODE * 4];
__device__ float g_as2[NNODE];
__device__ float g_ad2[NNODE];
__device__ float g_den2[NNODE];
__device__ float g_stats[512];   // [sum1(128) | sq1(128) | sum2(128) | sq2(128)]

__device__ __forceinline__ void redAdd4(float* p, float a, float b, float c, float d) {
    asm volatile("red.global.add.v4.f32 [%0], {%1, %2, %3, %4};"
                 :: "l"(p), "f"(a), "f"(b), "f"(c), "f"(d) : "memory");
}

// ---------------- init: zero accumulators ----------------
__global__ void init1(int N) {
    int idx = blockIdx.x * blockDim.x + threadIdx.x;
    if (idx < N * 128) g_out1[idx] = 0.f;
    if (idx < N * 4)   g_den1[idx] = 0.f;
    if (idx < 512)     g_stats[idx] = 0.f;
}
__global__ void init2(int N) {
    int idx = blockIdx.x * blockDim.x + threadIdx.x;
    if (idx < N * 128) g_out2[idx] = 0.f;
    if (idx < N)       g_den2[idx] = 0.f;
}

// ---------------- GEMM core macro pieces --------------------------------------
// block = 128 threads, 128 rows/block. W fully in SMEM (64KB), X tile 32x128.
// thread (w = warp, l = lane): 8 rows x 4 consecutive cols.

#define GEMM_PROLOGUE                                                          \
    extern __shared__ float sm[];                                              \
    float* Ws = sm;                                                            \
    float* Xs = sm + 16384;                                                    \
    int tid = threadIdx.x;                                                     \
    float4* Ws4 = (float4*)Ws;                                                 \
    const float4* W4 = (const float4*)W;                                       \
    for (int i = tid; i < 4096; i += 128) Ws4[i] = W4[i];                      \
    int w = tid >> 5, l = tid & 31;                                            \
    int rb0 = blockIdx.x * 128;

#define GEMM_TILE_LOAD                                                         \
    __syncthreads();                                                           \
    {                                                                          \
        float4* Xs4 = (float4*)Xs;                                             \
        for (int i = tid; i < 1024; i += 128) {                                \
            int r = i >> 5, cc = i & 31;                                       \
            int row = rbase + r;                                               \
            Xs4[i] = (row < nrows) ? ((const float4*)(A + (long)row * 128))[cc]\
                                   : make_float4(0.f, 0.f, 0.f, 0.f);          \
        }                                                                      \
    }                                                                          \
    __syncthreads();

#define GEMM_MAINLOOP                                                          \
    float acc[8][4];                                                           \
    _Pragma("unroll")                                                          \
    for (int r = 0; r < 8; r++)                                                \
        acc[r][0] = acc[r][1] = acc[r][2] = acc[r][3] = 0.f;                   \
    {                                                                          \
        const float* xrow = Xs + (w * 8) * 128;                                \
        _Pragma("unroll 4")                                                    \
        for (int k = 0; k < 128; k++) {                                        \
            float4 wv = Ws4[k * 32 + l];                                       \
            _Pragma("unroll")                                                  \
            for (int r = 0; r < 8; r++) {                                      \
                float xv = xrow[r * 128 + k];                                  \
                acc[r][0] = fmaf(xv, wv.x, acc[r][0]);                         \
                acc[r][1] = fmaf(xv, wv.y, acc[r][1]);                         \
                acc[r][2] = fmaf(xv, wv.z, acc[r][2]);                         \
                acc[r][3] = fmaf(xv, wv.w, acc[r][3]);                         \
            }                                                                  \
        }                                                                      \
    }

// residual GEMM: C = A@W + bias
__global__ void gemm128_bias(const float* __restrict__ A, const float* __restrict__ W,
                             const float* __restrict__ bias, float* __restrict__ C,
                             int nrows) {
    GEMM_PROLOGUE
    float4 bv = ((const float4*)bias)[l];
    for (int t = 0; t < 4; t++) {
        int rbase = rb0 + t * 32;
        GEMM_TILE_LOAD
        GEMM_MAINLOOP
#pragma unroll
        for (int r = 0; r < 8; r++) {
            int row = rbase + w * 8 + r;
            if (row < nrows) {
                float4 o = make_float4(acc[r][0] + bv.x, acc[r][1] + bv.y,
                                       acc[r][2] + bv.z, acc[r][3] + bv.w);
                ((float4*)(C + (long)row * 128))[l] = o;
            }
        }
    }
}

// conv1 GEMM: C = A@W1, epilogue computes 4-head attention logits (shfl over 8 lanes)
__global__ void gemm128_a4(const float* __restrict__ A, const float* __restrict__ W,
                           const float* __restrict__ att_s, const float* __restrict__ att_d,
                           float* __restrict__ C, int nrows) {
    GEMM_PROLOGUE
    float4 aS = ((const float4*)att_s)[l];   // att[head=l>>3][(l&7)*4 .. +3]
    float4 aD = ((const float4*)att_d)[l];
    for (int t = 0; t < 4; t++) {
        int rbase = rb0 + t * 32;
        GEMM_TILE_LOAD
        GEMM_MAINLOOP
#pragma unroll
        for (int r = 0; r < 8; r++) {
            int row = rbase + w * 8 + r;
            float ps = acc[r][0] * aS.x + acc[r][1] * aS.y + acc[r][2] * aS.z + acc[r][3] * aS.w;
            float pd = acc[r][0] * aD.x + acc[r][1] * aD.y + acc[r][2] * aD.z + acc[r][3] * aD.w;
#pragma unroll
            for (int off = 4; off; off >>= 1) {
                ps += __shfl_down_sync(0xffffffffu, ps, off, 8);
                pd += __shfl_down_sync(0xffffffffu, pd, off, 8);
            }
            if (row < nrows) {
                ((float4*)(C + (long)row * 128))[l] =
                    make_float4(acc[r][0], acc[r][1], acc[r][2], acc[r][3]);
                if ((l & 7) == 0) {
                    g_as1[row * 4 + (l >> 3)] = ps;
                    g_ad1[row * 4 + (l >> 3)] = pd;
                }
            }
        }
    }
}

// conv2 GEMM: C = A@W2, epilogue computes single-head logits (full-warp shfl)
__global__ void gemm128_a1(const float* __restrict__ A, const float* __restrict__ W,
                           const float* __restrict__ att_s, const float* __restrict__ att_d,
                           float* __restrict__ C, int nrows) {
    GEMM_PROLOGUE
    float4 aS = ((const float4*)att_s)[l];
    float4 aD = ((const float4*)att_d)[l];
    for (int t = 0; t < 4; t++) {
        int rbase = rb0 + t * 32;
        GEMM_TILE_LOAD
        GEMM_MAINLOOP
#pragma unroll
        for (int r = 0; r < 8; r++) {
            int row = rbase + w * 8 + r;
            float ps = acc[r][0] * aS.x + acc[r][1] * aS.y + acc[r][2] * aS.z + acc[r][3] * aS.w;
            float pd = acc[r][0] * aD.x + acc[r][1] * aD.y + acc[r][2] * aD.z + acc[r][3] * aD.w;
#pragma unroll
            for (int off = 16; off; off >>= 1) {
                ps += __shfl_down_sync(0xffffffffu, ps, off);
                pd += __shfl_down_sync(0xffffffffu, pd, off);
            }
            if (row < nrows) {
                ((float4*)(C + (long)row * 128))[l] =
                    make_float4(acc[r][0], acc[r][1], acc[r][2], acc[r][3]);
                if (l == 0) { g_as2[row] = ps; g_ad2[row] = pd; }
            }
        }
    }
}

// ---------------- GEMM: C[N,32] = A[N,128] @ W[128,32] (+bias) -----------------
__global__ void gemm32(const float* __restrict__ A, const float* __restrict__ W,
                       const float* __restrict__ bias, float* __restrict__ C,
                       int nrows) {
    __shared__ float Ws[128 * 32];
    __shared__ float Xs[32 * 128];
    int tid = threadIdx.x;
    for (int i = tid; i < 4096; i += 128) Ws[i] = W[i];
    int w = tid >> 5, l = tid & 31;
    float bv = bias[l];
    int rb0 = blockIdx.x * 128;

    for (int t = 0; t < 4; t++) {
        int rbase = rb0 + t * 32;
        __syncthreads();
        float4* Xs4 = (float4*)Xs;
        for (int i = tid; i < 1024; i += 128) {
            int r = i >> 5, cc = i & 31;
            int row = rbase + r;
            Xs4[i] = (row < nrows) ? ((const float4*)(A + (long)row * 128))[cc]
                                   : make_float4(0.f, 0.f, 0.f, 0.f);
        }
        __syncthreads();
        float acc[8] = {};
#pragma unroll 4
        for (int k = 0; k < 128; k++) {
            float wv = Ws[k * 32 + l];
#pragma unroll
            for (int r = 0; r < 8; r++)
                acc[r] = fmaf(Xs[(w * 8 + r) * 128 + k], wv, acc[r]);
        }
#pragma unroll
        for (int r = 0; r < 8; r++) {
            int row = rbase + w * 8 + r;
            if (row < nrows) C[(long)row * 32 + l] = acc[r] + bv;
        }
    }
}

// ---------------- fused edge pass: exp + denom + message scatter ---------------
// warp per edge. No max-subtraction (logits are O(6); exp is safe in fp32).
__device__ __forceinline__ void edge_sd(const int* ei, int E, int e, int& s, int& d) {
    if (e < E) { s = ei[e]; d = ei[E + e]; }
    else       { s = d = e - E; }   // appended self-loop
}

__global__ void scatter1(const int* __restrict__ ei, int E, int N) {
    long gid = (long)blockIdx.x * blockDim.x + threadIdx.x;
    int e = (int)(gid >> 5), l = (int)(gid & 31);
    if (e >= E + N) return;
    int s, d; edge_sd(ei, E, e, s, d);
    int head = l >> 3;
    float v = __ldg(g_as1 + s * 4 + head) + __ldg(g_ad1 + d * 4 + head);
    v = v > 0.f ? v : NEG_SLOPE * v;
    float ee = __expf(v);
    if ((l & 7) == 0) atomicAdd(&g_den1[d * 4 + head], ee);
    float4 hv = *(const float4*)(g_h1 + (long)s * 128 + l * 4);
    redAdd4(g_out1 + (long)d * 128 + l * 4, hv.x * ee, hv.y * ee, hv.z * ee, hv.w * ee);
}

__global__ void scatter2(const int* __restrict__ ei, int E, int N) {
    long gid = (long)blockIdx.x * blockDim.x + threadIdx.x;
    int e = (int)(gid >> 5), l = (int)(gid & 31);
    if (e >= E + N) return;
    int s, d; edge_sd(ei, E, e, s, d);
    float v = __ldg(g_as2 + s) + __ldg(g_ad2 + d);
    v = v > 0.f ? v : NEG_SLOPE * v;
    float ee = __expf(v);
    if (l == 0) atomicAdd(&g_den2[d], ee);
    float4 hv = *(const float4*)(g_h2 + (long)s * 128 + l * 4);
    redAdd4(g_out2 + (long)d * 128 + l * 4, hv.x * ee, hv.y * ee, hv.z * ee, hv.w * ee);
}

// ---------------- batch norm (normalization by den folded in) ------------------
__global__ void bn1_reduce(const float* __restrict__ bias, int N) {
    int c = threadIdx.x;
    int r0 = blockIdx.x * 256;
    int r1 = min(r0 + 256, N);
    float s = 0.f, q = 0.f;
    float b = bias[c];
    for (int r = r0; r < r1; r++) {
        float inv = __fdividef(1.f, g_den1[r * 4 + (c >> 5)] + 1e-16f);
        float v = g_out1[(long)r * 128 + c] * inv + b;
        s += v; q += v * v;
    }
    atomicAdd(&g_stats[c], s);
    atomicAdd(&g_stats[128 + c], q);
}

__global__ void bn1_apply(const float* __restrict__ bias,
                          const float* __restrict__ gamma,
                          const float* __restrict__ beta, int N) {
    long idx = (long)blockIdx.x * blockDim.x + threadIdx.x;
    if (idx >= (long)N * 128) return;
    int c = (int)(idx & 127);
    int r = (int)(idx >> 7);
    float inv = __fdividef(1.f, g_den1[r * 4 + (c >> 5)] + 1e-16f);
    float v = g_out1[idx] * inv + bias[c];
    float invN = 1.f / (float)N;
    float mu = g_stats[c] * invN;
    float var = g_stats[128 + c] * invN - mu * mu;
    float sc = gamma[c] * rsqrtf(var + BN_EPS);
    v = (v - mu) * sc + beta[c];
    g_out1[idx] = v > 0.f ? v : 0.f;
}

__global__ void bn2_reduce(const float* __restrict__ bias, int N) {
    int c = threadIdx.x;
    int r0 = blockIdx.x * 256;
    int r1 = min(r0 + 256, N);
    float s = 0.f, q = 0.f;
    float b = bias[c];
    for (int r = r0; r < r1; r++) {
        float inv = __fdividef(1.f, g_den2[r] + 1e-16f);
        float v = g_out2[(long)r * 128 + c] * inv + b;
        s += v; q += v * v;
    }
    atomicAdd(&g_stats[256 + c], s);
    atomicAdd(&g_stats[384 + c], q);
}

// bn2 + relu + residual-add + *1/sqrt(2) fused; writes g_z
__global__ void bn2_apply_res(const float* __restrict__ bias,
                              const float* __restrict__ gamma,
                              const float* __restrict__ beta, int N) {
    long idx = (long)blockIdx.x * blockDim.x + threadIdx.x;
    if (idx >= (long)N * 128) return;
    int c = (int)(idx & 127);
    int r = (int)(idx >> 7);
    float inv = __fdividef(1.f, g_den2[r] + 1e-16f);
    float v = g_out2[idx] * inv + bias[c];
    float invN = 1.f / (float)N;
    float mu = g_stats[256 + c] * invN;
    float var = g_stats[384 + c] * invN - mu * mu;
    float sc = gamma[c] * rsqrtf(var + BN_EPS);
    v = (v - mu) * sc + beta[c];
    v = v > 0.f ? v : 0.f;
    g_z[idx] = (v + g_res[idx]) * INV_SQRT2;
}

// ---------------- launch ------------------------------------------------------
extern "C" void kernel_launch(void* const* d_in, const int* in_sizes, int n_in,
                              void* d_out, int out_size) {
    const float* x        = (const float*)d_in[0];
    const int*   ei       = (const int*)  d_in[1];
    const float* W1       = (const float*)d_in[2];
    const float* att_src1 = (const float*)d_in[3];
    const float* att_dst1 = (const float*)d_in[4];
    const float* bias1    = (const float*)d_in[5];
    const float* W2       = (const float*)d_in[6];
    const float* att_src2 = (const float*)d_in[7];
    const float* att_dst2 = (const float*)d_in[8];
    const float* bias2    = (const float*)d_in[9];
    const float* gamma1   = (const float*)d_in[10];
    const float* beta1    = (const float*)d_in[11];
    const float* gamma2   = (const float*)d_in[12];
    const float* beta2    = (const float*)d_in[13];
    const float* W_res    = (const float*)d_in[14];
    const float* b_res    = (const float*)d_in[15];
    const float* W_fin    = (const float*)d_in[16];
    const float* b_fin    = (const float*)d_in[17];
    float* out = (float*)d_out;

    int N = in_sizes[0] / 128;
    int E = in_sizes[1] / 2;
    int tot = E + N;

    float *p_h1, *p_out1, *p_h2, *p_res, *p_z;
    cudaGetSymbolAddress((void**)&p_h1,   g_h1);
    cudaGetSymbolAddress((void**)&p_out1, g_out1);
    cudaGetSymbolAddress((void**)&p_h2,   g_h2);
    cudaGetSymbolAddress((void**)&p_res,  g_res);
    cudaGetSymbolAddress((void**)&p_z,    g_z);

    const int GEMM_SMEM = (16384 + 4096) * 4;  // 80KB
    cudaFuncSetAttribute(gemm128_bias, cudaFuncAttributeMaxDynamicSharedMemorySize, GEMM_SMEM);
    cudaFuncSetAttribute(gemm128_a4,   cudaFuncAttributeMaxDynamicSharedMemorySize, GEMM_SMEM);
    cudaFuncSetAttribute(gemm128_a1,   cudaFuncAttributeMaxDynamicSharedMemorySize, GEMM_SMEM);

    int sw = (int)(((long)tot * 32 + 255) / 256); // warp-per-edge grids
    int nb128 = (N * 128 + 255) / 256;            // element-wise over N*128
    int gb = (N + 127) / 128;                     // gemm row blocks
    int bnb = (N + 255) / 256;                    // bn reduce blocks

    init1<<<nb128, 256>>>(N);
    init2<<<nb128, 256>>>(N);

    // conv1
    gemm128_bias<<<gb, 128, GEMM_SMEM>>>(x, W_res, b_res, p_res, N);   // residual
    gemm128_a4<<<gb, 128, GEMM_SMEM>>>(x, W1, att_src1, att_dst1, p_h1, N);
    scatter1<<<sw, 256>>>(ei, E, N);
    bn1_reduce<<<bnb, 128>>>(bias1, N);
    bn1_apply<<<nb128, 256>>>(bias1, gamma1, beta1, N);

    // conv2
    gemm128_a1<<<gb, 128, GEMM_SMEM>>>(p_out1, W2, att_src2, att_dst2, p_h2, N);
    scatter2<<<sw, 256>>>(ei, E, N);
    bn2_reduce<<<bnb, 128>>>(bias2, N);
    bn2_apply_res<<<nb128, 256>>>(bias2, gamma2, beta2, N);

    // final projection
    gemm32<<<gb, 128>>>(p_z, W_fin, b_fin, out, N);
}

// round 3
// speedup vs baseline: 1.1038x; 1.1038x over previous
#include <cuda_runtime.h>

#define NNODE 50000
#define NEDGE 800000
#define NEG_SLOPE 0.2f
#define BN_EPS 1e-5f
#define INV_SQRT2 0.7071067811865476f

// ---------------- scratch (device globals: no allocations allowed) -------------
__device__ float g_h1  [NNODE * 128];
__device__ float g_out1[NNODE * 128];   // raw msg accum -> normalized in BN
__device__ float g_h2  [NNODE * 128];
__device__ float g_out2[NNODE * 128];
__device__ float g_res [NNODE * 128];
__device__ float g_z   [NNODE * 128];
__device__ float g_as1[NNODE * 4];
__device__ float g_ad1[NNODE * 4];
__device__ float g_den1[NNODE * 4];     // raw sum -> inverted by inv_den1
__device__ float g_as2[NNODE];
__device__ float g_ad2[NNODE];
__device__ float g_den2[NNODE];         // raw sum -> inverted by inv_den2
__device__ float g_stats[512];   // [sum1(128) | sq1(128) | sum2(128) | sq2(128)]

__device__ __forceinline__ void redAdd4(float* p, float a, float b, float c, float d) {
    asm volatile("red.global.add.v4.f32 [%0], {%1, %2, %3, %4};"
                 :: "l"(p), "f"(a), "f"(b), "f"(c), "f"(d) : "memory");
}

// ---------------- init: zero accumulators ----------------
__global__ void init1(int N) {
    int idx = blockIdx.x * blockDim.x + threadIdx.x;
    if (idx < N * 128) g_out1[idx] = 0.f;
    if (idx < N * 4)   g_den1[idx] = 0.f;
    if (idx < 512)     g_stats[idx] = 0.f;
}
__global__ void init2(int N) {
    int idx = blockIdx.x * blockDim.x + threadIdx.x;
    if (idx < N * 128) g_out2[idx] = 0.f;
    if (idx < N)       g_den2[idx] = 0.f;
}

// invert denominators once per node (keeps MUFU out of the N*128 BN passes)
__global__ void inv_den1(int N) {
    int idx = blockIdx.x * blockDim.x + threadIdx.x;
    if (idx < N * 4) g_den1[idx] = __fdividef(1.f, g_den1[idx] + 1e-16f);
}
__global__ void inv_den2(int N) {
    int idx = blockIdx.x * blockDim.x + threadIdx.x;
    if (idx < N) g_den2[idx] = __fdividef(1.f, g_den2[idx] + 1e-16f);
}

// ---------------- GEMM core ----------------------------------------------------
// 256 threads (8 warps), 256 rows/block. W[128x128] in SMEM (64KB),
// X tile 64x128 (32KB). Each thread: 8 rows x 4 consecutive cols.
// Inner loop: float4 X and W loads -> 12 LDS.128 per 128 FMA.

#define GEMM_SMEM_BYTES ((16384 + 8192) * 4)   // 96KB

#define GEMM_PROLOGUE                                                          \
    extern __shared__ float sm[];                                              \
    float* Ws = sm;              /* 128*128 */                                  \
    float* Xs = sm + 16384;      /* 64*128  */                                  \
    int tid = threadIdx.x;                                                      \
    float4* Ws4 = (float4*)Ws;                                                  \
    const float4* W4 = (const float4*)W;                                        \
    for (int i = tid; i < 4096; i += 256) Ws4[i] = W4[i];                       \
    int w = tid >> 5, l = tid & 31;                                             \
    int rb0 = blockIdx.x * 256;

#define GEMM_TILE_LOAD                                                          \
    __syncthreads();                                                            \
    {                                                                           \
        float4* Xs4w = (float4*)Xs;                                             \
        for (int i = tid; i < 2048; i += 256) {                                 \
            int r = i >> 5, cc = i & 31;                                        \
            int row = rbase + r;                                                \
            Xs4w[i] = (row < nrows) ? ((const float4*)(A + (long)row * 128))[cc]\
                                    : make_float4(0.f, 0.f, 0.f, 0.f);          \
        }                                                                       \
    }                                                                           \
    __syncthreads();

#define GEMM_MAINLOOP                                                          \
    float acc[8][4];                                                            \
    _Pragma("unroll")                                                           \
    for (int r = 0; r < 8; r++)                                                 \
        acc[r][0] = acc[r][1] = acc[r][2] = acc[r][3] = 0.f;                    \
    {                                                                           \
        const float4* Xr4 = (const float4*)Xs + (w * 8) * 32;                   \
        _Pragma("unroll 4")                                                     \
        for (int k4 = 0; k4 < 32; k4++) {                                       \
            float4 w0 = Ws4[(k4 * 4 + 0) * 32 + l];                             \
            float4 w1 = Ws4[(k4 * 4 + 1) * 32 + l];                             \
            float4 w2 = Ws4[(k4 * 4 + 2) * 32 + l];                             \
            float4 w3 = Ws4[(k4 * 4 + 3) * 32 + l];                             \
            _Pragma("unroll")                                                   \
            for (int r = 0; r < 8; r++) {                                       \
                float4 xv = Xr4[r * 32 + k4];                                   \
                acc[r][0] = fmaf(xv.x, w0.x, acc[r][0]);                        \
                acc[r][0] = fmaf(xv.y, w1.x, acc[r][0]);                        \
                acc[r][0] = fmaf(xv.z, w2.x, acc[r][0]);                        \
                acc[r][0] = fmaf(xv.w, w3.x, acc[r][0]);                        \
                acc[r][1] = fmaf(xv.x, w0.y, acc[r][1]);                        \
                acc[r][1] = fmaf(xv.y, w1.y, acc[r][1]);                        \
                acc[r][1] = fmaf(xv.z, w2.y, acc[r][1]);                        \
                acc[r][1] = fmaf(xv.w, w3.y, acc[r][1]);                        \
                acc[r][2] = fmaf(xv.x, w0.z, acc[r][2]);                        \
                acc[r][2] = fmaf(xv.y, w1.z, acc[r][2]);                        \
                acc[r][2] = fmaf(xv.z, w2.z, acc[r][2]);                        \
                acc[r][2] = fmaf(xv.w, w3.z, acc[r][2]);                        \
                acc[r][3] = fmaf(xv.x, w0.w, acc[r][3]);                        \
                acc[r][3] = fmaf(xv.y, w1.w, acc[r][3]);                        \
                acc[r][3] = fmaf(xv.z, w2.w, acc[r][3]);                        \
                acc[r][3] = fmaf(xv.w, w3.w, acc[r][3]);                        \
            }                                                                   \
        }                                                                       \
    }

// residual GEMM: C = A@W + bias
__global__ void __launch_bounds__(256, 2)
gemm128_bias(const float* __restrict__ A, const float* __restrict__ W,
             const float* __restrict__ bias, float* __restrict__ C, int nrows) {
    GEMM_PROLOGUE
    float4 bv = ((const float4*)bias)[l];
    for (int t = 0; t < 4; t++) {
        int rbase = rb0 + t * 64;
        GEMM_TILE_LOAD
        GEMM_MAINLOOP
#pragma unroll
        for (int r = 0; r < 8; r++) {
            int row = rbase + w * 8 + r;
            if (row < nrows) {
                float4 o = make_float4(acc[r][0] + bv.x, acc[r][1] + bv.y,
                                       acc[r][2] + bv.z, acc[r][3] + bv.w);
                ((float4*)(C + (long)row * 128))[l] = o;
            }
        }
    }
}

// conv1 GEMM: C = A@W1, epilogue computes 4-head attention logits (shfl over 8 lanes)
__global__ void __launch_bounds__(256, 2)
gemm128_a4(const float* __restrict__ A, const float* __restrict__ W,
           const float* __restrict__ att_s, const float* __restrict__ att_d,
           float* __restrict__ C, int nrows) {
    GEMM_PROLOGUE
    float4 aS = ((const float4*)att_s)[l];   // att[head=l>>3][(l&7)*4 .. +3]
    float4 aD = ((const float4*)att_d)[l];
    for (int t = 0; t < 4; t++) {
        int rbase = rb0 + t * 64;
        GEMM_TILE_LOAD
        GEMM_MAINLOOP
#pragma unroll
        for (int r = 0; r < 8; r++) {
            int row = rbase + w * 8 + r;
            float ps = acc[r][0] * aS.x + acc[r][1] * aS.y + acc[r][2] * aS.z + acc[r][3] * aS.w;
            float pd = acc[r][0] * aD.x + acc[r][1] * aD.y + acc[r][2] * aD.z + acc[r][3] * aD.w;
#pragma unroll
            for (int off = 4; off; off >>= 1) {
                ps += __shfl_down_sync(0xffffffffu, ps, off, 8);
                pd += __shfl_down_sync(0xffffffffu, pd, off, 8);
            }
            if (row < nrows) {
                ((float4*)(C + (long)row * 128))[l] =
                    make_float4(acc[r][0], acc[r][1], acc[r][2], acc[r][3]);
                if ((l & 7) == 0) {
                    g_as1[row * 4 + (l >> 3)] = ps;
                    g_ad1[row * 4 + (l >> 3)] = pd;
                }
            }
        }
    }
}

// conv2 GEMM: C = A@W2, epilogue computes single-head logits (full-warp shfl)
__global__ void __launch_bounds__(256, 2)
gemm128_a1(const float* __restrict__ A, const float* __restrict__ W,
           const float* __restrict__ att_s, const float* __restrict__ att_d,
           float* __restrict__ C, int nrows) {
    GEMM_PROLOGUE
    float4 aS = ((const float4*)att_s)[l];
    float4 aD = ((const float4*)att_d)[l];
    for (int t = 0; t < 4; t++) {
        int rbase = rb0 + t * 64;
        GEMM_TILE_LOAD
        GEMM_MAINLOOP
#pragma unroll
        for (int r = 0; r < 8; r++) {
            int row = rbase + w * 8 + r;
            float ps = acc[r][0] * aS.x + acc[r][1] * aS.y + acc[r][2] * aS.z + acc[r][3] * aS.w;
            float pd = acc[r][0] * aD.x + acc[r][1] * aD.y + acc[r][2] * aD.z + acc[r][3] * aD.w;
#pragma unroll
            for (int off = 16; off; off >>= 1) {
                ps += __shfl_down_sync(0xffffffffu, ps, off);
                pd += __shfl_down_sync(0xffffffffu, pd, off);
            }
            if (row < nrows) {
                ((float4*)(C + (long)row * 128))[l] =
                    make_float4(acc[r][0], acc[r][1], acc[r][2], acc[r][3]);
                if (l == 0) { g_as2[row] = ps; g_ad2[row] = pd; }
            }
        }
    }
}

// ---------------- GEMM: C[N,32] = A[N,128] @ W[128,32] (+bias) -----------------
__global__ void gemm32(const float* __restrict__ A, const float* __restrict__ W,
                       const float* __restrict__ bias, float* __restrict__ C,
                       int nrows) {
    __shared__ float Ws[128 * 32];
    __shared__ float Xs[32 * 128];
    int tid = threadIdx.x;
    for (int i = tid; i < 4096; i += 128) Ws[i] = W[i];
    int w = tid >> 5, l = tid & 31;
    float bv = bias[l];
    int rb0 = blockIdx.x * 128;

    for (int t = 0; t < 4; t++) {
        int rbase = rb0 + t * 32;
        __syncthreads();
        float4* Xs4 = (float4*)Xs;
        for (int i = tid; i < 1024; i += 128) {
            int r = i >> 5, cc = i & 31;
            int row = rbase + r;
            Xs4[i] = (row < nrows) ? ((const float4*)(A + (long)row * 128))[cc]
                                   : make_float4(0.f, 0.f, 0.f, 0.f);
        }
        __syncthreads();
        float acc[8] = {};
#pragma unroll 4
        for (int k = 0; k < 128; k++) {
            float wv = Ws[k * 32 + l];
#pragma unroll
            for (int r = 0; r < 8; r++)
                acc[r] = fmaf(Xs[(w * 8 + r) * 128 + k], wv, acc[r]);
        }
#pragma unroll
        for (int r = 0; r < 8; r++) {
            int row = rbase + w * 8 + r;
            if (row < nrows) C[(long)row * 32 + l] = acc[r] + bv;
        }
    }
}

// ---------------- fused edge pass: exp + denom + message scatter ---------------
// warp per edge. No max-subtraction (logits are O(6); exp is safe in fp32).
__device__ __forceinline__ void edge_sd(const int* ei, int E, int e, int& s, int& d) {
    if (e < E) { s = ei[e]; d = ei[E + e]; }
    else       { s = d = e - E; }   // appended self-loop
}

__global__ void scatter1(const int* __restrict__ ei, int E, int N) {
    long gid = (long)blockIdx.x * blockDim.x + threadIdx.x;
    int e = (int)(gid >> 5), l = (int)(gid & 31);
    if (e >= E + N) return;
    int s, d; edge_sd(ei, E, e, s, d);
    int head = l >> 3;
    float v = __ldg(g_as1 + s * 4 + head) + __ldg(g_ad1 + d * 4 + head);
    v = v > 0.f ? v : NEG_SLOPE * v;
    float ee = __expf(v);
    if ((l & 7) == 0) atomicAdd(&g_den1[d * 4 + head], ee);
    float4 hv = *(const float4*)(g_h1 + (long)s * 128 + l * 4);
    redAdd4(g_out1 + (long)d * 128 + l * 4, hv.x * ee, hv.y * ee, hv.z * ee, hv.w * ee);
}

__global__ void scatter2(const int* __restrict__ ei, int E, int N) {
    long gid = (long)blockIdx.x * blockDim.x + threadIdx.x;
    int e = (int)(gid >> 5), l = (int)(gid & 31);
    if (e >= E + N) return;
    int s, d; edge_sd(ei, E, e, s, d);
    float v = __ldg(g_as2 + s) + __ldg(g_ad2 + d);
    v = v > 0.f ? v : NEG_SLOPE * v;
    float ee = __expf(v);
    if (l == 0) atomicAdd(&g_den2[d], ee);
    float4 hv = *(const float4*)(g_h2 + (long)s * 128 + l * 4);
    redAdd4(g_out2 + (long)d * 128 + l * 4, hv.x * ee, hv.y * ee, hv.z * ee, hv.w * ee);
}

// ---------------- batch norm (den pre-inverted; multiply only) -----------------
__global__ void bn1_reduce(const float* __restrict__ bias, int N) {
    int c = threadIdx.x;
    int r0 = blockIdx.x * 256;
    int r1 = min(r0 + 256, N);
    float s = 0.f, q = 0.f;
    float b = bias[c];
    int hsel = c >> 5;
    for (int r = r0; r < r1; r++) {
        float v = g_out1[(long)r * 128 + c] * g_den1[r * 4 + hsel] + b;
        s += v; q += v * v;
    }
    atomicAdd(&g_stats[c], s);
    atomicAdd(&g_stats[128 + c], q);
}

__global__ void bn1_apply(const float* __restrict__ bias,
                          const float* __restrict__ gamma,
                          const float* __restrict__ beta, int N) {
    long idx = (long)blockIdx.x * blockDim.x + threadIdx.x;
    if (idx >= (long)N * 128) return;
    int c = (int)(idx & 127);
    int r = (int)(idx >> 7);
    float v = g_out1[idx] * g_den1[r * 4 + (c >> 5)] + bias[c];
    float invN = 1.f / (float)N;
    float mu = g_stats[c] * invN;
    float var = g_stats[128 + c] * invN - mu * mu;
    float sc = gamma[c] * rsqrtf(var + BN_EPS);
    v = (v - mu) * sc + beta[c];
    g_out1[idx] = v > 0.f ? v : 0.f;
}

__global__ void bn2_reduce(const float* __restrict__ bias, int N) {
    int c = threadIdx.x;
    int r0 = blockIdx.x * 256;
    int r1 = min(r0 + 256, N);
    float s = 0.f, q = 0.f;
    float b = bias[c];
    for (int r = r0; r < r1; r++) {
        float v = g_out2[(long)r * 128 + c] * g_den2[r] + b;
        s += v; q += v * v;
    }
    atomicAdd(&g_stats[256 + c], s);
    atomicAdd(&g_stats[384 + c], q);
}

// bn2 + relu + residual-add + *1/sqrt(2) fused; writes g_z
__global__ void bn2_apply_res(const float* __restrict__ bias,
                              const float* __restrict__ gamma,
                              const float* __restrict__ beta, int N) {
    long idx = (long)blockIdx.x * blockDim.x + threadIdx.x;
    if (idx >= (long)N * 128) return;
    int c = (int)(idx & 127);
    int r = (int)(idx >> 7);
    float v = g_out2[idx] * g_den2[r] + bias[c];
    float invN = 1.f / (float)N;
    float mu = g_stats[256 + c] * invN;
    float var = g_stats[384 + c] * invN - mu * mu;
    float sc = gamma[c] * rsqrtf(var + BN_EPS);
    v = (v - mu) * sc + beta[c];
    v = v > 0.f ? v : 0.f;
    g_z[idx] = (v + g_res[idx]) * INV_SQRT2;
}

// ---------------- launch ------------------------------------------------------
extern "C" void kernel_launch(void* const* d_in, const int* in_sizes, int n_in,
                              void* d_out, int out_size) {
    const float* x        = (const float*)d_in[0];
    const int*   ei       = (const int*)  d_in[1];
    const float* W1       = (const float*)d_in[2];
    const float* att_src1 = (const float*)d_in[3];
    const float* att_dst1 = (const float*)d_in[4];
    const float* bias1    = (const float*)d_in[5];
    const float* W2       = (const float*)d_in[6];
    const float* att_src2 = (const float*)d_in[7];
    const float* att_dst2 = (const float*)d_in[8];
    const float* bias2    = (const float*)d_in[9];
    const float* gamma1   = (const float*)d_in[10];
    const float* beta1    = (const float*)d_in[11];
    const float* gamma2   = (const float*)d_in[12];
    const float* beta2    = (const float*)d_in[13];
    const float* W_res    = (const float*)d_in[14];
    const float* b_res    = (const float*)d_in[15];
    const float* W_fin    = (const float*)d_in[16];
    const float* b_fin    = (const float*)d_in[17];
    float* out = (float*)d_out;

    int N = in_sizes[0] / 128;
    int E = in_sizes[1] / 2;
    int tot = E + N;

    float *p_h1, *p_out1, *p_h2, *p_res, *p_z;
    cudaGetSymbolAddress((void**)&p_h1,   g_h1);
    cudaGetSymbolAddress((void**)&p_out1, g_out1);
    cudaGetSymbolAddress((void**)&p_h2,   g_h2);
    cudaGetSymbolAddress((void**)&p_res,  g_res);
    cudaGetSymbolAddress((void**)&p_z,    g_z);

    cudaFuncSetAttribute(gemm128_bias, cudaFuncAttributeMaxDynamicSharedMemorySize, GEMM_SMEM_BYTES);
    cudaFuncSetAttribute(gemm128_a4,   cudaFuncAttributeMaxDynamicSharedMemorySize, GEMM_SMEM_BYTES);
    cudaFuncSetAttribute(gemm128_a1,   cudaFuncAttributeMaxDynamicSharedMemorySize, GEMM_SMEM_BYTES);

    int sw = (int)(((long)tot * 32 + 255) / 256); // warp-per-edge grids
    int nb128 = (N * 128 + 255) / 256;            // element-wise over N*128
    int gb = (N + 255) / 256;                     // gemm row blocks (256 rows)
    int bnb = (N + 255) / 256;                    // bn reduce blocks

    init1<<<nb128, 256>>>(N);
    init2<<<nb128, 256>>>(N);

    // conv1
    gemm128_bias<<<gb, 256, GEMM_SMEM_BYTES>>>(x, W_res, b_res, p_res, N);   // residual
    gemm128_a4<<<gb, 256, GEMM_SMEM_BYTES>>>(x, W1, att_src1, att_dst1, p_h1, N);
    scatter1<<<sw, 256>>>(ei, E, N);
    inv_den1<<<(N * 4 + 255) / 256, 256>>>(N);
    bn1_reduce<<<bnb, 128>>>(bias1, N);
    bn1_apply<<<nb128, 256>>>(bias1, gamma1, beta1, N);

    // conv2
    gemm128_a1<<<gb, 256, GEMM_SMEM_BYTES>>>(p_out1, W2, att_src2, att_dst2, p_h2, N);
    scatter2<<<sw, 256>>>(ei, E, N);
    inv_den2<<<(N + 255) / 256, 256>>>(N);
    bn2_reduce<<<bnb, 128>>>(bias2, N);
    bn2_apply_res<<<nb128, 256>>>(bias2, gamma2, beta2, N);

    // final projection
    gemm32<<<(N + 127) / 128, 128>>>(p_z, W_fin, b_fin, out, N);
}

// round 4
// speedup vs baseline: 1.1755x; 1.0650x over previous
#include <cuda_runtime.h>

#define NNODE 50000
#define NEDGE 800000
#define NEG_SLOPE 0.2f
#define BN_EPS 1e-5f
#define INV_SQRT2 0.7071067811865476f

// ---------------- scratch (device globals: no allocations allowed) -------------
__device__ float g_h1  [NNODE * 128];
__device__ float g_out1[NNODE * 128];   // raw weighted-msg accum (pre-BN)
__device__ float g_h2  [NNODE * 128];
__device__ float g_out2[NNODE * 128];
__device__ float g_res [NNODE * 128];
__device__ float g_as1[NNODE * 4];
__device__ float g_ad1[NNODE * 4];
__device__ float g_den1[NNODE * 4];     // raw sum -> inverted inside bn1_reduce
__device__ float g_as2[NNODE];
__device__ float g_ad2[NNODE];
__device__ float g_den2[NNODE];         // raw sum -> inverted inside bn2_reduce
__device__ float g_stats[512];   // [sum1(128) | sq1(128) | sum2(128) | sq2(128)]

__device__ __forceinline__ void redAdd4(float* p, float a, float b, float c, float d) {
    asm volatile("red.global.add.v4.f32 [%0], {%1, %2, %3, %4};"
                 :: "l"(p), "f"(a), "f"(b), "f"(c), "f"(d) : "memory");
}
__device__ __forceinline__ float dot4(float4 a, float4 b) {
    return a.x * b.x + a.y * b.y + a.z * b.z + a.w * b.w;
}
#define FMA4(a, s, v) { (a).x = fmaf((s), (v).x, (a).x); (a).y = fmaf((s), (v).y, (a).y); \
                        (a).z = fmaf((s), (v).z, (a).z); (a).w = fmaf((s), (v).w, (a).w); }

// ---------------- init: zero all accumulators ----------------
__global__ void init_all(int N) {
    int idx = blockIdx.x * blockDim.x + threadIdx.x;
    if (idx < N * 128) { g_out1[idx] = 0.f; g_out2[idx] = 0.f; }
    if (idx < N * 4)   g_den1[idx] = 0.f;
    if (idx < N)       { g_den2[idx] = 0.f; g_as2[idx] = 0.f; g_ad2[idx] = 0.f; }
    if (idx < 512)     g_stats[idx] = 0.f;
}

// ---------------- GEMM v3 core ---------------------------------------------------
// Tile: 128 rows x 64 cols (blockIdx.y = column half). 128 threads (4 warps).
// Per-thread: 8 rows x 8 cols. K streamed in 2 chunks of 64.
// SMEM: Ws4[128k][16 float4] (32KB) + Xs4[128r][16 float4] (32KB) = 64KB -> 3 CTAs/SM.
// Inner: per k4 (4 k's): 8 W LDS.128 + 8 X LDS.128 + 256 FMA (ratio 16).

#define G3_SMEM (4096 * 16)   // 64KB

#define G3_SETUP                                                                 \
    extern __shared__ float4 sm4[];                                              \
    float4* Ws4 = sm4;                                                           \
    float4* Xs4 = sm4 + 2048;                                                    \
    const int tid = threadIdx.x;                                                 \
    const int l = tid & 31, w = tid >> 5;                                        \
    const int cg = l & 7, rg = l >> 3;                                           \
    const int ch = blockIdx.y;                                                   \
    const int rb0 = blockIdx.x * 128;                                            \
    const int rowloc = w * 32 + rg * 8;                                          \
    const float4* W4 = (const float4*)W;                                         \
    const float4* A4 = (const float4*)A;                                         \
    for (int i = tid; i < 2048; i += 128) {                                      \
        int k = i >> 4, j = i & 15;                                              \
        Ws4[i] = W4[k * 32 + ch * 16 + j];                                       \
    }                                                                            \
    float4 acc0[8], acc1[8];                                                     \
    _Pragma("unroll")                                                            \
    for (int r = 0; r < 8; r++) {                                                \
        acc0[r] = make_float4(0.f, 0.f, 0.f, 0.f);                               \
        acc1[r] = make_float4(0.f, 0.f, 0.f, 0.f);                               \
    }

// XLOAD_EXPR(row, c, kk) must yield a float4 for K-chunk c, float4-index kk.
#define G3_MAIN(XLOAD_STMT)                                                      \
    for (int c = 0; c < 2; c++) {                                                \
        __syncthreads();                                                         \
        for (int i = tid; i < 2048; i += 128) {                                  \
            int r = i >> 4, kk = i & 15;                                         \
            int row = rb0 + r;                                                   \
            float4 xv = make_float4(0.f, 0.f, 0.f, 0.f);                         \
            if (row < nrows) { XLOAD_STMT }                                      \
            Xs4[i] = xv;                                                         \
        }                                                                        \
        __syncthreads();                                                         \
        _Pragma("unroll 4")                                                      \
        for (int k4 = 0; k4 < 16; k4++) {                                        \
            const float4* wp = Ws4 + (c * 64 + k4 * 4) * 16 + cg * 2;            \
            float4 wa0 = wp[0],  wb0 = wp[1];                                    \
            float4 wa1 = wp[16], wb1 = wp[17];                                   \
            float4 wa2 = wp[32], wb2 = wp[33];                                   \
            float4 wa3 = wp[48], wb3 = wp[49];                                   \
            _Pragma("unroll")                                                    \
            for (int r = 0; r < 8; r++) {                                        \
                float4 xv = Xs4[(rowloc + r) * 16 + k4];                         \
                FMA4(acc0[r], xv.x, wa0); FMA4(acc1[r], xv.x, wb0);              \
                FMA4(acc0[r], xv.y, wa1); FMA4(acc1[r], xv.y, wb1);              \
                FMA4(acc0[r], xv.z, wa2); FMA4(acc1[r], xv.z, wb2);              \
                FMA4(acc0[r], xv.w, wa3); FMA4(acc1[r], xv.w, wb3);              \
            }                                                                    \
        }                                                                        \
    }

#define XLOAD_PLAIN  { xv = A4[(long)row * 32 + c * 16 + kk]; }

// ---- residual GEMM: C = x @ W_res + b_res -------------------------------------
__global__ void __launch_bounds__(128, 3)
gemm_res(const float* __restrict__ A, const float* __restrict__ W,
         const float* __restrict__ bias, float* __restrict__ C, int nrows) {
    G3_SETUP
    G3_MAIN(XLOAD_PLAIN)
    float4 bv0 = ((const float4*)bias)[ch * 16 + cg * 2];
    float4 bv1 = ((const float4*)bias)[ch * 16 + cg * 2 + 1];
#pragma unroll
    for (int r = 0; r < 8; r++) {
        int row = rb0 + rowloc + r;
        if (row < nrows) {
            float4 o0 = make_float4(acc0[r].x + bv0.x, acc0[r].y + bv0.y,
                                    acc0[r].z + bv0.z, acc0[r].w + bv0.w);
            float4 o1 = make_float4(acc1[r].x + bv1.x, acc1[r].y + bv1.y,
                                    acc1[r].z + bv1.z, acc1[r].w + bv1.w);
            ((float4*)C)[(long)row * 32 + ch * 16 + cg * 2]     = o0;
            ((float4*)C)[(long)row * 32 + ch * 16 + cg * 2 + 1] = o1;
        }
    }
}

// ---- conv1 GEMM: C = x @ W1, 4-head logits in epilogue -------------------------
// Column half ch covers heads {2ch, 2ch+1}; thread's 8 cols lie in one head.
__global__ void __launch_bounds__(128, 3)
gemm_a4(const float* __restrict__ A, const float* __restrict__ W,
        const float* __restrict__ att_s, const float* __restrict__ att_d,
        float* __restrict__ C, int nrows) {
    G3_SETUP
    G3_MAIN(XLOAD_PLAIN)
    float4 aS0 = ((const float4*)att_s)[ch * 16 + cg * 2];
    float4 aS1 = ((const float4*)att_s)[ch * 16 + cg * 2 + 1];
    float4 aD0 = ((const float4*)att_d)[ch * 16 + cg * 2];
    float4 aD1 = ((const float4*)att_d)[ch * 16 + cg * 2 + 1];
    int hl = cg >> 2;
#pragma unroll
    for (int r = 0; r < 8; r++) {
        int row = rb0 + rowloc + r;
        float ps = dot4(acc0[r], aS0) + dot4(acc1[r], aS1);
        float pd = dot4(acc0[r], aD0) + dot4(acc1[r], aD1);
        ps += __shfl_down_sync(0xffffffffu, ps, 2, 4);
        ps += __shfl_down_sync(0xffffffffu, ps, 1, 4);
        pd += __shfl_down_sync(0xffffffffu, pd, 2, 4);
        pd += __shfl_down_sync(0xffffffffu, pd, 1, 4);
        if (row < nrows) {
            ((float4*)C)[(long)row * 32 + ch * 16 + cg * 2]     = acc0[r];
            ((float4*)C)[(long)row * 32 + ch * 16 + cg * 2 + 1] = acc1[r];
            if ((cg & 3) == 0) {
                g_as1[row * 4 + ch * 2 + hl] = ps;
                g_ad1[row * 4 + ch * 2 + hl] = pd;
            }
        }
    }
}

// ---- conv2 GEMM, fused: X = relu(BN1(out1/den1 + bias1)); logits via atomicAdd --
__global__ void __launch_bounds__(128, 3)
gemm_a1f(const float* __restrict__ A, const float* __restrict__ W,
         const float* __restrict__ att_s, const float* __restrict__ att_d,
         const float* __restrict__ bias, const float* __restrict__ gamma,
         const float* __restrict__ beta, float* __restrict__ C, int nrows) {
    __shared__ float s_sc[128], s_off[128];
    {
        int c = threadIdx.x;   // 128 threads == 128 channels
        float invN = 1.f / (float)nrows;
        float mu = g_stats[c] * invN;
        float var = g_stats[128 + c] * invN - mu * mu;
        float sc = gamma[c] * rsqrtf(var + BN_EPS);
        s_sc[c] = sc;
        s_off[c] = (bias[c] - mu) * sc + beta[c];
    }
    G3_SETUP
    G3_MAIN({
        float4 raw = A4[(long)row * 32 + c * 16 + kk];
        int ch0 = (c * 16 + kk) * 4;
        float inv = g_den1[row * 4 + (ch0 >> 5)];
        xv.x = fmaxf(fmaf(raw.x * inv, s_sc[ch0 + 0], s_off[ch0 + 0]), 0.f);
        xv.y = fmaxf(fmaf(raw.y * inv, s_sc[ch0 + 1], s_off[ch0 + 1]), 0.f);
        xv.z = fmaxf(fmaf(raw.z * inv, s_sc[ch0 + 2], s_off[ch0 + 2]), 0.f);
        xv.w = fmaxf(fmaf(raw.w * inv, s_sc[ch0 + 3], s_off[ch0 + 3]), 0.f);
    })
    float4 aS0 = ((const float4*)att_s)[ch * 16 + cg * 2];
    float4 aS1 = ((const float4*)att_s)[ch * 16 + cg * 2 + 1];
    float4 aD0 = ((const float4*)att_d)[ch * 16 + cg * 2];
    float4 aD1 = ((const float4*)att_d)[ch * 16 + cg * 2 + 1];
#pragma unroll
    for (int r = 0; r < 8; r++) {
        int row = rb0 + rowloc + r;
        float ps = dot4(acc0[r], aS0) + dot4(acc1[r], aS1);
        float pd = dot4(acc0[r], aD0) + dot4(acc1[r], aD1);
        ps += __shfl_down_sync(0xffffffffu, ps, 4, 8);
        ps += __shfl_down_sync(0xffffffffu, ps, 2, 8);
        ps += __shfl_down_sync(0xffffffffu, ps, 1, 8);
        pd += __shfl_down_sync(0xffffffffu, pd, 4, 8);
        pd += __shfl_down_sync(0xffffffffu, pd, 2, 8);
        pd += __shfl_down_sync(0xffffffffu, pd, 1, 8);
        if (row < nrows) {
            ((float4*)C)[(long)row * 32 + ch * 16 + cg * 2]     = acc0[r];
            ((float4*)C)[(long)row * 32 + ch * 16 + cg * 2 + 1] = acc1[r];
            if (cg == 0) {
                atomicAdd(&g_as2[row], ps);
                atomicAdd(&g_ad2[row], pd);
            }
        }
    }
}

// ---- final GEMM [N,128]x[128,32], fused BN2+relu+residual+1/sqrt2 on X-load ----
__global__ void gemm32f(const float* __restrict__ A, const float* __restrict__ W,
                        const float* __restrict__ bias_fin,
                        const float* __restrict__ bias2,
                        const float* __restrict__ gamma2,
                        const float* __restrict__ beta2,
                        const float* __restrict__ Rres,
                        float* __restrict__ C, int nrows) {
    __shared__ float Ws[128 * 32];
    __shared__ float Xs[32 * 128];
    __shared__ float s_sc[128], s_off[128];
    int tid = threadIdx.x;
    {
        float invN = 1.f / (float)nrows;
        float mu = g_stats[256 + tid] * invN;
        float var = g_stats[384 + tid] * invN - mu * mu;
        float sc = gamma2[tid] * rsqrtf(var + BN_EPS);
        s_sc[tid] = sc;
        s_off[tid] = (bias2[tid] - mu) * sc + beta2[tid];
    }
    for (int i = tid; i < 4096; i += 128) Ws[i] = W[i];
    int w = tid >> 5, l = tid & 31;
    float bv = bias_fin[l];
    int rb0 = blockIdx.x * 128;
    const float4* A4 = (const float4*)A;
    const float4* R4 = (const float4*)Rres;

    for (int t = 0; t < 4; t++) {
        int rbase = rb0 + t * 32;
        __syncthreads();
        float4* Xs4 = (float4*)Xs;
        for (int i = tid; i < 1024; i += 128) {
            int r = i >> 5, cc = i & 31;
            int row = rbase + r;
            float4 xv = make_float4(0.f, 0.f, 0.f, 0.f);
            if (row < nrows) {
                float4 raw = A4[(long)row * 32 + cc];
                float4 rs  = R4[(long)row * 32 + cc];
                float inv = g_den2[row];
                int c0 = cc * 4;
                float v;
                v = fmaxf(fmaf(raw.x * inv, s_sc[c0 + 0], s_off[c0 + 0]), 0.f);
                xv.x = (v + rs.x) * INV_SQRT2;
                v = fmaxf(fmaf(raw.y * inv, s_sc[c0 + 1], s_off[c0 + 1]), 0.f);
                xv.y = (v + rs.y) * INV_SQRT2;
                v = fmaxf(fmaf(raw.z * inv, s_sc[c0 + 2], s_off[c0 + 2]), 0.f);
                xv.z = (v + rs.z) * INV_SQRT2;
                v = fmaxf(fmaf(raw.w * inv, s_sc[c0 + 3], s_off[c0 + 3]), 0.f);
                xv.w = (v + rs.w) * INV_SQRT2;
            }
            Xs4[i] = xv;
        }
        __syncthreads();
        float acc[8] = {};
#pragma unroll 4
        for (int k = 0; k < 128; k++) {
            float wv = Ws[k * 32 + l];
#pragma unroll
            for (int r = 0; r < 8; r++)
                acc[r] = fmaf(Xs[(w * 8 + r) * 128 + k], wv, acc[r]);
        }
#pragma unroll
        for (int r = 0; r < 8; r++) {
            int row = rbase + w * 8 + r;
            if (row < nrows) C[(long)row * 32 + l] = acc[r] + bv;
        }
    }
}

// ---------------- fused edge pass: exp + denom + message scatter ---------------
__device__ __forceinline__ void edge_sd(const int* ei, int E, int e, int& s, int& d) {
    if (e < E) { s = ei[e]; d = ei[E + e]; }
    else       { s = d = e - E; }   // appended self-loop
}

__global__ void scatter1(const int* __restrict__ ei, int E, int N) {
    long gid = (long)blockIdx.x * blockDim.x + threadIdx.x;
    int e = (int)(gid >> 5), l = (int)(gid & 31);
    if (e >= E + N) return;
    int s, d; edge_sd(ei, E, e, s, d);
    int head = l >> 3;
    float v = __ldg(g_as1 + s * 4 + head) + __ldg(g_ad1 + d * 4 + head);
    v = v > 0.f ? v : NEG_SLOPE * v;
    float ee = __expf(v);
    if ((l & 7) == 0) atomicAdd(&g_den1[d * 4 + head], ee);
    float4 hv = *(const float4*)(g_h1 + (long)s * 128 + l * 4);
    redAdd4(g_out1 + (long)d * 128 + l * 4, hv.x * ee, hv.y * ee, hv.z * ee, hv.w * ee);
}

__global__ void scatter2(const int* __restrict__ ei, int E, int N) {
    long gid = (long)blockIdx.x * blockDim.x + threadIdx.x;
    int e = (int)(gid >> 5), l = (int)(gid & 31);
    if (e >= E + N) return;
    int s, d; edge_sd(ei, E, e, s, d);
    float v = __ldg(g_as2 + s) + __ldg(g_ad2 + d);
    v = v > 0.f ? v : NEG_SLOPE * v;
    float ee = __expf(v);
    if (l == 0) atomicAdd(&g_den2[d], ee);
    float4 hv = *(const float4*)(g_h2 + (long)s * 128 + l * 4);
    redAdd4(g_out2 + (long)d * 128 + l * 4, hv.x * ee, hv.y * ee, hv.z * ee, hv.w * ee);
}

// ---------------- batch norm reductions (den inversion merged) -----------------
__global__ void bn1_reduce(const float* __restrict__ bias, int N) {
    int c = threadIdx.x;
    int r0 = blockIdx.x * 256;
    int r1 = min(r0 + 256, N);
    // invert this block's den1 entries (rows are block-exclusive)
    for (int i = r0 * 4 + c; i < r1 * 4; i += 128)
        g_den1[i] = __fdividef(1.f, g_den1[i] + 1e-16f);
    __syncthreads();
    float s = 0.f, q = 0.f;
    float b = bias[c];
    int hsel = c >> 5;
    for (int r = r0; r < r1; r++) {
        float v = g_out1[(long)r * 128 + c] * g_den1[r * 4 + hsel] + b;
        s += v; q += v * v;
    }
    atomicAdd(&g_stats[c], s);
    atomicAdd(&g_stats[128 + c], q);
}

__global__ void bn2_reduce(const float* __restrict__ bias, int N) {
    int c = threadIdx.x;
    int r0 = blockIdx.x * 256;
    int r1 = min(r0 + 256, N);
    for (int i = r0 + c; i < r1; i += 128)
        g_den2[i] = __fdividef(1.f, g_den2[i] + 1e-16f);
    __syncthreads();
    float s = 0.f, q = 0.f;
    float b = bias[c];
    for (int r = r0; r < r1; r++) {
        float v = g_out2[(long)r * 128 + c] * g_den2[r] + b;
        s += v; q += v * v;
    }
    atomicAdd(&g_stats[256 + c], s);
    atomicAdd(&g_stats[384 + c], q);
}

// ---------------- launch ------------------------------------------------------
extern "C" void kernel_launch(void* const* d_in, const int* in_sizes, int n_in,
                              void* d_out, int out_size) {
    const float* x        = (const float*)d_in[0];
    const int*   ei       = (const int*)  d_in[1];
    const float* W1       = (const float*)d_in[2];
    const float* att_src1 = (const float*)d_in[3];
    const float* att_dst1 = (const float*)d_in[4];
    const float* bias1    = (const float*)d_in[5];
    const float* W2       = (const float*)d_in[6];
    const float* att_src2 = (const float*)d_in[7];
    const float* att_dst2 = (const float*)d_in[8];
    const float* bias2    = (const float*)d_in[9];
    const float* gamma1   = (const float*)d_in[10];
    const float* beta1    = (const float*)d_in[11];
    const float* gamma2   = (const float*)d_in[12];
    const float* beta2    = (const float*)d_in[13];
    const float* W_res    = (const float*)d_in[14];
    const float* b_res    = (const float*)d_in[15];
    const float* W_fin    = (const float*)d_in[16];
    const float* b_fin    = (const float*)d_in[17];
    float* out = (float*)d_out;

    int N = in_sizes[0] / 128;
    int E = in_sizes[1] / 2;
    int tot = E + N;

    float *p_h1, *p_out1, *p_h2, *p_out2, *p_res;
    cudaGetSymbolAddress((void**)&p_h1,   g_h1);
    cudaGetSymbolAddress((void**)&p_out1, g_out1);
    cudaGetSymbolAddress((void**)&p_h2,   g_h2);
    cudaGetSymbolAddress((void**)&p_out2, g_out2);
    cudaGetSymbolAddress((void**)&p_res,  g_res);

    cudaFuncSetAttribute(gemm_res, cudaFuncAttributeMaxDynamicSharedMemorySize, G3_SMEM);
    cudaFuncSetAttribute(gemm_a4,  cudaFuncAttributeMaxDynamicSharedMemorySize, G3_SMEM);
    cudaFuncSetAttribute(gemm_a1f, cudaFuncAttributeMaxDynamicSharedMemorySize, G3_SMEM);

    int sw = (int)(((long)tot * 32 + 255) / 256); // warp-per-edge grid
    int nb128 = (N * 128 + 255) / 256;            // element-wise over N*128
    dim3 gg((N + 127) / 128, 2);                  // GEMM v3 grid (col-split)
    int bnb = (N + 255) / 256;                    // bn reduce blocks

    init_all<<<nb128, 256>>>(N);

    // conv1
    gemm_res<<<gg, 128, G3_SMEM>>>(x, W_res, b_res, p_res, N);
    gemm_a4<<<gg, 128, G3_SMEM>>>(x, W1, att_src1, att_dst1, p_h1, N);
    scatter1<<<sw, 256>>>(ei, E, N);
    bn1_reduce<<<bnb, 128>>>(bias1, N);

    // conv2 (BN1+relu fused into X-load)
    gemm_a1f<<<gg, 128, G3_SMEM>>>(p_out1, W2, att_src2, att_dst2,
                                   bias1, gamma1, beta1, p_h2, N);
    scatter2<<<sw, 256>>>(ei, E, N);
    bn2_reduce<<<bnb, 128>>>(bias2, N);

    // final projection (BN2+relu+residual+1/sqrt2 fused into X-load)
    gemm32f<<<(N + 127) / 128, 128>>>(p_out2, W_fin, b_fin,
                                      bias2, gamma2, beta2, p_res, out, N);
}

// round 5
// speedup vs baseline: 1.3683x; 1.1639x over previous
#include <cuda_runtime.h>

#define NNODE 50000
#define NEDGE 800000
#define TOTE  (NNODE + NEDGE)
#define NEG_SLOPE 0.2f
#define BN_EPS 1e-5f
#define INV_SQRT2 0.7071067811865476f

// ---------------- scratch (device globals: no allocations allowed) -------------
__device__ float g_h1  [NNODE * 128];
__device__ float g_out1[NNODE * 128];   // normalized conv1 output (+bias1)
__device__ float g_h2  [NNODE * 128];
__device__ float g_out2[NNODE * 128];   // normalized conv2 output (+bias2)
__device__ float g_res [NNODE * 128];
__device__ float g_as1[NNODE * 4];
__device__ float g_ad1[NNODE * 4];
__device__ float g_as2[NNODE];
__device__ float g_ad2[NNODE];
__device__ float g_stats[512];   // [sum1(128) | sq1(128) | sum2(128) | sq2(128)]
__device__ int   g_cnt   [NNODE];       // histogram, then fill cursor
__device__ int   g_rowptr[NNODE + 1];
__device__ int   g_csrc  [TOTE];        // src node per dst-sorted edge

__device__ __forceinline__ float dot4(float4 a, float4 b) {
    return a.x * b.x + a.y * b.y + a.z * b.z + a.w * b.w;
}
#define FMA4(a, s, v) { (a).x = fmaf((s), (v).x, (a).x); (a).y = fmaf((s), (v).y, (a).y); \
                        (a).z = fmaf((s), (v).z, (a).z); (a).w = fmaf((s), (v).w, (a).w); }

// ---------------- init: cnt=1 (self-loop), zero small arrays -------------------
__global__ void init_small(int N) {
    int idx = blockIdx.x * blockDim.x + threadIdx.x;
    if (idx < N) { g_cnt[idx] = 1; g_as2[idx] = 0.f; g_ad2[idx] = 0.f; }
    if (idx < 512) g_stats[idx] = 0.f;
}

// ---------------- CSR build ----------------------------------------------------
__global__ void hist(const int* __restrict__ ei, int E) {
    int e = blockIdx.x * blockDim.x + threadIdx.x;
    if (e < E) atomicAdd(&g_cnt[ei[E + e]], 1);
}

// one block, 1024 threads: exclusive scan of g_cnt into g_rowptr; cnt := cursor
__global__ void scan_rowptr(int N) {
    __shared__ int s_sum[1024];
    int t = threadIdx.x;
    int chunk = (N + 1023) >> 10;
    int b0 = t * chunk, b1 = min(b0 + chunk, N);
    int s = 0;
    for (int i = b0; i < b1; i++) s += g_cnt[i];
    s_sum[t] = s;
    __syncthreads();
    for (int off = 1; off < 1024; off <<= 1) {
        int v = (t >= off) ? s_sum[t - off] : 0;
        __syncthreads();
        s_sum[t] += v;
        __syncthreads();
    }
    int run = (t == 0) ? 0 : s_sum[t - 1];
    for (int i = b0; i < b1; i++) {
        int c = g_cnt[i];
        g_rowptr[i] = run;
        g_cnt[i] = run;          // cursor for fill
        run += c;
    }
    if (t == 1023) g_rowptr[N] = run;
}

__global__ void fill_csr(const int* __restrict__ ei, int E, int N) {
    int e = blockIdx.x * blockDim.x + threadIdx.x;
    if (e >= E + N) return;
    int s, d;
    if (e < E) { s = ei[e]; d = ei[E + e]; }
    else       { s = d = e - E; }
    int pos = atomicAdd(&g_cnt[d], 1);
    g_csrc[pos] = s;
}

// ---------------- GEMM v3 core ---------------------------------------------------
// Tile: 128 rows x 64 cols (blockIdx.y = column half). 128 threads (4 warps).
// Per-thread: 8 rows x 8 cols. K streamed in 2 chunks of 64.
// SMEM 64KB -> 3 CTAs/SM.

#define G3_SMEM (4096 * 16)   // 64KB

#define G3_SETUP                                                                 \
    extern __shared__ float4 sm4[];                                              \
    float4* Ws4 = sm4;                                                           \
    float4* Xs4 = sm4 + 2048;                                                    \
    const int tid = threadIdx.x;                                                 \
    const int l = tid & 31, w = tid >> 5;                                        \
    const int cg = l & 7, rg = l >> 3;                                           \
    const int ch = blockIdx.y;                                                   \
    const int rb0 = blockIdx.x * 128;                                            \
    const int rowloc = w * 32 + rg * 8;                                          \
    const float4* W4 = (const float4*)W;                                         \
    const float4* A4 = (const float4*)A;                                         \
    for (int i = tid; i < 2048; i += 128) {                                      \
        int k = i >> 4, j = i & 15;                                              \
        Ws4[i] = W4[k * 32 + ch * 16 + j];                                       \
    }                                                                            \
    float4 acc0[8], acc1[8];                                                     \
    _Pragma("unroll")                                                            \
    for (int r = 0; r < 8; r++) {                                                \
        acc0[r] = make_float4(0.f, 0.f, 0.f, 0.f);                               \
        acc1[r] = make_float4(0.f, 0.f, 0.f, 0.f);                               \
    }

#define G3_MAIN(XLOAD_STMT)                                                      \
    for (int c = 0; c < 2; c++) {                                                \
        __syncthreads();                                                         \
        for (int i = tid; i < 2048; i += 128) {                                  \
            int r = i >> 4, kk = i & 15;                                         \
            int row = rb0 + r;                                                   \
            float4 xv = make_float4(0.f, 0.f, 0.f, 0.f);                         \
            if (row < nrows) { XLOAD_STMT }                                      \
            Xs4[i] = xv;                                                         \
        }                                                                        \
        __syncthreads();                                                         \
        _Pragma("unroll 4")                                                      \
        for (int k4 = 0; k4 < 16; k4++) {                                        \
            const float4* wp = Ws4 + (c * 64 + k4 * 4) * 16 + cg * 2;            \
            float4 wa0 = wp[0],  wb0 = wp[1];                                    \
            float4 wa1 = wp[16], wb1 = wp[17];                                   \
            float4 wa2 = wp[32], wb2 = wp[33];                                   \
            float4 wa3 = wp[48], wb3 = wp[49];                                   \
            _Pragma("unroll")                                                    \
            for (int r = 0; r < 8; r++) {                                        \
                float4 xv = Xs4[(rowloc + r) * 16 + k4];                         \
                FMA4(acc0[r], xv.x, wa0); FMA4(acc1[r], xv.x, wb0);              \
                FMA4(acc0[r], xv.y, wa1); FMA4(acc1[r], xv.y, wb1);              \
                FMA4(acc0[r], xv.z, wa2); FMA4(acc1[r], xv.z, wb2);              \
                FMA4(acc0[r], xv.w, wa3); FMA4(acc1[r], xv.w, wb3);              \
            }                                                                    \
        }                                                                        \
    }

#define XLOAD_PLAIN  { xv = A4[(long)row * 32 + c * 16 + kk]; }

// ---- residual GEMM: C = x @ W_res + b_res -------------------------------------
__global__ void __launch_bounds__(128, 3)
gemm_res(const float* __restrict__ A, const float* __restrict__ W,
         const float* __restrict__ bias, float* __restrict__ C, int nrows) {
    G3_SETUP
    G3_MAIN(XLOAD_PLAIN)
    float4 bv0 = ((const float4*)bias)[ch * 16 + cg * 2];
    float4 bv1 = ((const float4*)bias)[ch * 16 + cg * 2 + 1];
#pragma unroll
    for (int r = 0; r < 8; r++) {
        int row = rb0 + rowloc + r;
        if (row < nrows) {
            float4 o0 = make_float4(acc0[r].x + bv0.x, acc0[r].y + bv0.y,
                                    acc0[r].z + bv0.z, acc0[r].w + bv0.w);
            float4 o1 = make_float4(acc1[r].x + bv1.x, acc1[r].y + bv1.y,
                                    acc1[r].z + bv1.z, acc1[r].w + bv1.w);
            ((float4*)C)[(long)row * 32 + ch * 16 + cg * 2]     = o0;
            ((float4*)C)[(long)row * 32 + ch * 16 + cg * 2 + 1] = o1;
        }
    }
}

// ---- conv1 GEMM: C = x @ W1, 4-head logits in epilogue -------------------------
__global__ void __launch_bounds__(128, 3)
gemm_a4(const float* __restrict__ A, const float* __restrict__ W,
        const float* __restrict__ att_s, const float* __restrict__ att_d,
        float* __restrict__ C, int nrows) {
    G3_SETUP
    G3_MAIN(XLOAD_PLAIN)
    float4 aS0 = ((const float4*)att_s)[ch * 16 + cg * 2];
    float4 aS1 = ((const float4*)att_s)[ch * 16 + cg * 2 + 1];
    float4 aD0 = ((const float4*)att_d)[ch * 16 + cg * 2];
    float4 aD1 = ((const float4*)att_d)[ch * 16 + cg * 2 + 1];
    int hl = cg >> 2;
#pragma unroll
    for (int r = 0; r < 8; r++) {
        int row = rb0 + rowloc + r;
        float ps = dot4(acc0[r], aS0) + dot4(acc1[r], aS1);
        float pd = dot4(acc0[r], aD0) + dot4(acc1[r], aD1);
        ps += __shfl_down_sync(0xffffffffu, ps, 2, 4);
        ps += __shfl_down_sync(0xffffffffu, ps, 1, 4);
        pd += __shfl_down_sync(0xffffffffu, pd, 2, 4);
        pd += __shfl_down_sync(0xffffffffu, pd, 1, 4);
        if (row < nrows) {
            ((float4*)C)[(long)row * 32 + ch * 16 + cg * 2]     = acc0[r];
            ((float4*)C)[(long)row * 32 + ch * 16 + cg * 2 + 1] = acc1[r];
            if ((cg & 3) == 0) {
                g_as1[row * 4 + ch * 2 + hl] = ps;
                g_ad1[row * 4 + ch * 2 + hl] = pd;
            }
        }
    }
}

// ---- conv2 GEMM, fused: X = relu(BN1(out1)); logits via atomicAdd --------------
// out1 already contains normalized conv1 output + bias1.
__global__ void __launch_bounds__(128, 3)
gemm_a1f(const float* __restrict__ A, const float* __restrict__ W,
         const float* __restrict__ att_s, const float* __restrict__ att_d,
         const float* __restrict__ gamma, const float* __restrict__ beta,
         float* __restrict__ C, int nrows) {
    __shared__ float s_sc[128], s_off[128];
    {
        int c = threadIdx.x;
        float invN = 1.f / (float)nrows;
        float mu = g_stats[c] * invN;
        float var = g_stats[128 + c] * invN - mu * mu;
        float sc = gamma[c] * rsqrtf(var + BN_EPS);
        s_sc[c] = sc;
        s_off[c] = beta[c] - mu * sc;
    }
    G3_SETUP
    G3_MAIN({
        float4 raw = A4[(long)row * 32 + c * 16 + kk];
        int ch0 = (c * 16 + kk) * 4;
        xv.x = fmaxf(fmaf(raw.x, s_sc[ch0 + 0], s_off[ch0 + 0]), 0.f);
        xv.y = fmaxf(fmaf(raw.y, s_sc[ch0 + 1], s_off[ch0 + 1]), 0.f);
        xv.z = fmaxf(fmaf(raw.z, s_sc[ch0 + 2], s_off[ch0 + 2]), 0.f);
        xv.w = fmaxf(fmaf(raw.w, s_sc[ch0 + 3], s_off[ch0 + 3]), 0.f);
    })
    float4 aS0 = ((const float4*)att_s)[ch * 16 + cg * 2];
    float4 aS1 = ((const float4*)att_s)[ch * 16 + cg * 2 + 1];
    float4 aD0 = ((const float4*)att_d)[ch * 16 + cg * 2];
    float4 aD1 = ((const float4*)att_d)[ch * 16 + cg * 2 + 1];
#pragma unroll
    for (int r = 0; r < 8; r++) {
        int row = rb0 + rowloc + r;
        float ps = dot4(acc0[r], aS0) + dot4(acc1[r], aS1);
        float pd = dot4(acc0[r], aD0) + dot4(acc1[r], aD1);
        ps += __shfl_down_sync(0xffffffffu, ps, 4, 8);
        ps += __shfl_down_sync(0xffffffffu, ps, 2, 8);
        ps += __shfl_down_sync(0xffffffffu, ps, 1, 8);
        pd += __shfl_down_sync(0xffffffffu, pd, 4, 8);
        pd += __shfl_down_sync(0xffffffffu, pd, 2, 8);
        pd += __shfl_down_sync(0xffffffffu, pd, 1, 8);
        if (row < nrows) {
            ((float4*)C)[(long)row * 32 + ch * 16 + cg * 2]     = acc0[r];
            ((float4*)C)[(long)row * 32 + ch * 16 + cg * 2 + 1] = acc1[r];
            if (cg == 0) {
                atomicAdd(&g_as2[row], ps);
                atomicAdd(&g_ad2[row], pd);
            }
        }
    }
}

// ---- final GEMM [N,128]x[128,32], fused BN2+relu+residual+1/sqrt2 on X-load ----
// out2 already contains normalized conv2 output + bias2.
__global__ void gemm32f(const float* __restrict__ A, const float* __restrict__ W,
                        const float* __restrict__ bias_fin,
                        const float* __restrict__ gamma2,
                        const float* __restrict__ beta2,
                        const float* __restrict__ Rres,
                        float* __restrict__ C, int nrows) {
    __shared__ float Ws[128 * 32];
    __shared__ float Xs[32 * 128];
    __shared__ float s_sc[128], s_off[128];
    int tid = threadIdx.x;
    {
        float invN = 1.f / (float)nrows;
        float mu = g_stats[256 + tid] * invN;
        float var = g_stats[384 + tid] * invN - mu * mu;
        float sc = gamma2[tid] * rsqrtf(var + BN_EPS);
        s_sc[tid] = sc;
        s_off[tid] = beta2[tid] - mu * sc;
    }
    for (int i = tid; i < 4096; i += 128) Ws[i] = W[i];
    int w = tid >> 5, l = tid & 31;
    float bv = bias_fin[l];
    int rb0 = blockIdx.x * 128;
    const float4* A4 = (const float4*)A;
    const float4* R4 = (const float4*)Rres;

    for (int t = 0; t < 4; t++) {
        int rbase = rb0 + t * 32;
        __syncthreads();
        float4* Xs4 = (float4*)Xs;
        for (int i = tid; i < 1024; i += 128) {
            int r = i >> 5, cc = i & 31;
            int row = rbase + r;
            float4 xv = make_float4(0.f, 0.f, 0.f, 0.f);
            if (row < nrows) {
                float4 raw = A4[(long)row * 32 + cc];
                float4 rs  = R4[(long)row * 32 + cc];
                int c0 = cc * 4;
                float v;
                v = fmaxf(fmaf(raw.x, s_sc[c0 + 0], s_off[c0 + 0]), 0.f);
                xv.x = (v + rs.x) * INV_SQRT2;
                v = fmaxf(fmaf(raw.y, s_sc[c0 + 1], s_off[c0 + 1]), 0.f);
                xv.y = (v + rs.y) * INV_SQRT2;
                v = fmaxf(fmaf(raw.z, s_sc[c0 + 2], s_off[c0 + 2]), 0.f);
                xv.z = (v + rs.z) * INV_SQRT2;
                v = fmaxf(fmaf(raw.w, s_sc[c0 + 3], s_off[c0 + 3]), 0.f);
                xv.w = (v + rs.w) * INV_SQRT2;
            }
            Xs4[i] = xv;
        }
        __syncthreads();
        float acc[8] = {};
#pragma unroll 4
        for (int k = 0; k < 128; k++) {
            float wv = Ws[k * 32 + l];
#pragma unroll
            for (int r = 0; r < 8; r++)
                acc[r] = fmaf(Xs[(w * 8 + r) * 128 + k], wv, acc[r]);
        }
#pragma unroll
        for (int r = 0; r < 8; r++) {
            int row = rbase + w * 8 + r;
            if (row < nrows) C[(long)row * 32 + l] = acc[r] + bv;
        }
    }
}

// ---------------- atomic-free aggregation: warp per destination node ------------
// out[d] = (sum_e ee_h * h[src_e]) / (den_h + 1e-16) + bias
__global__ void agg1(const float* __restrict__ bias, int N) {
    int gw = (blockIdx.x * blockDim.x + threadIdx.x) >> 5;
    int l = threadIdx.x & 31;
    if (gw >= N) return;
    int beg = g_rowptr[gw], end = g_rowptr[gw + 1];
    float4 adv = *(const float4*)(g_ad1 + gw * 4);
    int head = l >> 3;
    float4 acc = make_float4(0.f, 0.f, 0.f, 0.f);
    float4 den = make_float4(0.f, 0.f, 0.f, 0.f);
    for (int base = beg; base < end; base += 32) {
        int e = base + l;
        int s = 0;
        float4 ee = make_float4(0.f, 0.f, 0.f, 0.f);
        if (e < end) {
            s = g_csrc[e];
            float4 as = *(const float4*)(g_as1 + s * 4);
            float vx = as.x + adv.x; vx = vx > 0.f ? vx : NEG_SLOPE * vx;
            float vy = as.y + adv.y; vy = vy > 0.f ? vy : NEG_SLOPE * vy;
            float vz = as.z + adv.z; vz = vz > 0.f ? vz : NEG_SLOPE * vz;
            float vw = as.w + adv.w; vw = vw > 0.f ? vw : NEG_SLOPE * vw;
            ee.x = __expf(vx); ee.y = __expf(vy);
            ee.z = __expf(vz); ee.w = __expf(vw);
            den.x += ee.x; den.y += ee.y; den.z += ee.z; den.w += ee.w;
        }
        int cnt = min(32, end - base);
        for (int j = 0; j < cnt; j++) {
            int ss   = __shfl_sync(0xffffffffu, s, j);
            float ex = __shfl_sync(0xffffffffu, ee.x, j);
            float ey = __shfl_sync(0xffffffffu, ee.y, j);
            float ez = __shfl_sync(0xffffffffu, ee.z, j);
            float ew = __shfl_sync(0xffffffffu, ee.w, j);
            float eh = head == 0 ? ex : head == 1 ? ey : head == 2 ? ez : ew;
            float4 hv = *(const float4*)(g_h1 + (long)ss * 128 + l * 4);
            FMA4(acc, eh, hv);
        }
    }
#pragma unroll
    for (int off = 16; off; off >>= 1) {
        den.x += __shfl_xor_sync(0xffffffffu, den.x, off);
        den.y += __shfl_xor_sync(0xffffffffu, den.y, off);
        den.z += __shfl_xor_sync(0xffffffffu, den.z, off);
        den.w += __shfl_xor_sync(0xffffffffu, den.w, off);
    }
    float dh = head == 0 ? den.x : head == 1 ? den.y : head == 2 ? den.z : den.w;
    float inv = __fdividef(1.f, dh + 1e-16f);
    float4 bv = ((const float4*)bias)[l];
    float4 o = make_float4(acc.x * inv + bv.x, acc.y * inv + bv.y,
                           acc.z * inv + bv.z, acc.w * inv + bv.w);
    ((float4*)g_out1)[(long)gw * 32 + l] = o;
}

__global__ void agg2(const float* __restrict__ bias, int N) {
    int gw = (blockIdx.x * blockDim.x + threadIdx.x) >> 5;
    int l = threadIdx.x & 31;
    if (gw >= N) return;
    int beg = g_rowptr[gw], end = g_rowptr[gw + 1];
    float adv = g_ad2[gw];
    float4 acc = make_float4(0.f, 0.f, 0.f, 0.f);
    float den = 0.f;
    for (int base = beg; base < end; base += 32) {
        int e = base + l;
        int s = 0;
        float ee = 0.f;
        if (e < end) {
            s = g_csrc[e];
            float v = __ldg(g_as2 + s) + adv;
            v = v > 0.f ? v : NEG_SLOPE * v;
            ee = __expf(v);
            den += ee;
        }
        int cnt = min(32, end - base);
        for (int j = 0; j < cnt; j++) {
            int ss   = __shfl_sync(0xffffffffu, s, j);
            float ej = __shfl_sync(0xffffffffu, ee, j);
            float4 hv = *(const float4*)(g_h2 + (long)ss * 128 + l * 4);
            FMA4(acc, ej, hv);
        }
    }
#pragma unroll
    for (int off = 16; off; off >>= 1)
        den += __shfl_xor_sync(0xffffffffu, den, off);
    float inv = __fdividef(1.f, den + 1e-16f);
    float4 bv = ((const float4*)bias)[l];
    float4 o = make_float4(acc.x * inv + bv.x, acc.y * inv + bv.y,
                           acc.z * inv + bv.z, acc.w * inv + bv.w);
    ((float4*)g_out2)[(long)gw * 32 + l] = o;
}

// ---------------- batch norm reductions (inputs already bias-included) ----------
__global__ void bn1_reduce(int N) {
    int c = threadIdx.x;
    int r0 = blockIdx.x * 256;
    int r1 = min(r0 + 256, N);
    float s = 0.f, q = 0.f;
    for (int r = r0; r < r1; r++) {
        float v = g_out1[(long)r * 128 + c];
        s += v; q += v * v;
    }
    atomicAdd(&g_stats[c], s);
    atomicAdd(&g_stats[128 + c], q);
}

__global__ void bn2_reduce(int N) {
    int c = threadIdx.x;
    int r0 = blockIdx.x * 256;
    int r1 = min(r0 + 256, N);
    float s = 0.f, q = 0.f;
    for (int r = r0; r < r1; r++) {
        float v = g_out2[(long)r * 128 + c];
        s += v; q += v * v;
    }
    atomicAdd(&g_stats[256 + c], s);
    atomicAdd(&g_stats[384 + c], q);
}

// ---------------- launch ------------------------------------------------------
extern "C" void kernel_launch(void* const* d_in, const int* in_sizes, int n_in,
                              void* d_out, int out_size) {
    const float* x        = (const float*)d_in[0];
    const int*   ei       = (const int*)  d_in[1];
    const float* W1       = (const float*)d_in[2];
    const float* att_src1 = (const float*)d_in[3];
    const float* att_dst1 = (const float*)d_in[4];
    const float* bias1    = (const float*)d_in[5];
    const float* W2       = (const float*)d_in[6];
    const float* att_src2 = (const float*)d_in[7];
    const float* att_dst2 = (const float*)d_in[8];
    const float* bias2    = (const float*)d_in[9];
    const float* gamma1   = (const float*)d_in[10];
    const float* beta1    = (const float*)d_in[11];
    const float* gamma2   = (const float*)d_in[12];
    const float* beta2    = (const float*)d_in[13];
    const float* W_res    = (const float*)d_in[14];
    const float* b_res    = (const float*)d_in[15];
    const float* W_fin    = (const float*)d_in[16];
    const float* b_fin    = (const float*)d_in[17];
    float* out = (float*)d_out;

    int N = in_sizes[0] / 128;
    int E = in_sizes[1] / 2;
    int tot = E + N;

    float *p_h1, *p_out1, *p_h2, *p_out2, *p_res;
    cudaGetSymbolAddress((void**)&p_h1,   g_h1);
    cudaGetSymbolAddress((void**)&p_out1, g_out1);
    cudaGetSymbolAddress((void**)&p_h2,   g_h2);
    cudaGetSymbolAddress((void**)&p_out2, g_out2);
    cudaGetSymbolAddress((void**)&p_res,  g_res);

    cudaFuncSetAttribute(gemm_res, cudaFuncAttributeMaxDynamicSharedMemorySize, G3_SMEM);
    cudaFuncSetAttribute(gemm_a4,  cudaFuncAttributeMaxDynamicSharedMemorySize, G3_SMEM);
    cudaFuncSetAttribute(gemm_a1f, cudaFuncAttributeMaxDynamicSharedMemorySize, G3_SMEM);

    dim3 gg((N + 127) / 128, 2);                  // GEMM v3 grid (col-split)
    int aw = (N * 32 + 255) / 256;                // warp-per-node agg grid
    int bnb = (N + 255) / 256;                    // bn reduce blocks

    // CSR build (shared by both convs)
    init_small<<<(N + 255) / 256, 256>>>(N);
    hist<<<(E + 255) / 256, 256>>>(ei, E);
    scan_rowptr<<<1, 1024>>>(N);
    fill_csr<<<(tot + 255) / 256, 256>>>(ei, E, N);

    // conv1
    gemm_res<<<gg, 128, G3_SMEM>>>(x, W_res, b_res, p_res, N);
    gemm_a4<<<gg, 128, G3_SMEM>>>(x, W1, att_src1, att_dst1, p_h1, N);
    agg1<<<aw, 256>>>(bias1, N);
    bn1_reduce<<<bnb, 128>>>(N);

    // conv2 (BN1+relu fused into X-load)
    gemm_a1f<<<gg, 128, G3_SMEM>>>(p_out1, W2, att_src2, att_dst2,
                                   gamma1, beta1, p_h2, N);
    agg2<<<aw, 256>>>(bias2, N);
    bn2_reduce<<<bnb, 128>>>(N);

    // final projection (BN2+relu+residual+1/sqrt2 fused into X-load)
    gemm32f<<<(N + 127) / 128, 128>>>(p_out2, W_fin, b_fin,
                                      gamma2, beta2, p_res, out, N);
}